// round 1
// baseline (speedup 1.0000x reference)
#include <cuda_runtime.h>

// ============================================================================
// NeuralCellularAutomata: out[b,w,h,o] = W2 @ relu(ConvFused(x) + b1f) + b2
// ConvFused = 16->128 3x3 conv with WF = W1x@Wx + W1y@Wy + W1i*delta(center)
// ============================================================================

#define TILE_W 8
#define TILE_H 16
#define NTHREADS 512
#define SMEM_FLOATS (18432 + 2880 + 2048 + 128 + 16)
#define SMEM_BYTES (SMEM_FLOATS * 4)

// Fused weights (precomputed per launch; deterministic).
// g_WF layout: [k][mm][chunk][4] with k = i*9+kh*3+kw in [0,144),
// hidden m = chunk*32 + mm*4 + j.
__device__ float g_WF[144 * 128];
__device__ float g_W2i[16 * 128];   // W2 interleaved same way per o-row
__device__ float g_B1f[128];

__global__ void prep_wf_kernel(const float* __restrict__ Wx,
                               const float* __restrict__ Wy,
                               const float* __restrict__ W1) {
    int idx = blockIdx.x * blockDim.x + threadIdx.x;
    if (idx >= 144 * 128) return;
    int k = idx >> 7;
    int r = idx & 127;
    int mm = r >> 4, chunk = (r >> 2) & 3, j = r & 3;
    int m = chunk * 32 + mm * 4 + j;
    int i = k / 9, kk = k - i * 9;
    const float* w1r = W1 + m * 48;
    float s = 0.f;
#pragma unroll
    for (int o = 0; o < 16; ++o) {
        s += w1r[o]      * Wx[(o * 16 + i) * 9 + kk];
        s += w1r[16 + o] * Wy[(o * 16 + i) * 9 + kk];
    }
    if (kk == 4) s += w1r[32 + i];  // identity-channel contribution (center tap)
    g_WF[idx] = s;
}

__global__ void prep_misc_kernel(const float* __restrict__ W1,
                                 const float* __restrict__ b1,
                                 const float* __restrict__ bx,
                                 const float* __restrict__ by,
                                 const float* __restrict__ W2) {
    int idx = blockIdx.x * blockDim.x + threadIdx.x;
    if (idx < 16 * 128) {
        int o = idx >> 7, r = idx & 127;
        int mm = r >> 4, chunk = (r >> 2) & 3, j = r & 3;
        int m = chunk * 32 + mm * 4 + j;
        g_W2i[idx] = W2[o * 128 + m];
    }
    if (idx < 128) {
        float s = b1[idx];
        const float* w1r = W1 + idx * 48;
#pragma unroll
        for (int o = 0; o < 16; ++o) s += w1r[o] * bx[o] + w1r[16 + o] * by[o];
        g_B1f[idx] = s;
    }
}

__device__ __forceinline__ unsigned long long fma2(unsigned long long a,
                                                   unsigned long long b,
                                                   unsigned long long c) {
    unsigned long long d;
    asm("fma.rn.f32x2 %0, %1, %2, %3;" : "=l"(d) : "l"(a), "l"(b), "l"(c));
    return d;
}

__device__ __forceinline__ unsigned long long pack2(float lo, float hi) {
    unsigned long long d;
    unsigned int a = __float_as_uint(lo), b = __float_as_uint(hi);
    asm("mov.b64 %0, {%1, %2};" : "=l"(d) : "r"(a), "r"(b));
    return d;
}

__global__ __launch_bounds__(NTHREADS, 2)
void nca_main_kernel(const float* __restrict__ x,
                     const float* __restrict__ b2g,
                     float* __restrict__ out) {
    extern __shared__ float smem[];
    float* sWF = smem;             // 18432 floats, interleaved [k][mm][chunk][4]
    float* sX  = smem + 18432;     // 16 x 18 x 10 halo tile
    float* sW2 = sX + 2880;        // 2048, interleaved [o][mm][chunk][4]
    float* sB1 = sW2 + 2048;       // 128
    float* sB2 = sB1 + 128;        // 16

    const int t = threadIdx.x;
    const int bid = blockIdx.x;
    const int b = bid >> 7;
    const int tile = bid & 127;
    const int w0 = (tile >> 3) * TILE_W;   // 16 w-tiles
    const int h0 = (tile & 7) * TILE_H;    // 8 h-tiles

    // ---- stage weights ----
    {
        const float4* src = (const float4*)g_WF;
        float4* dst = (float4*)sWF;
#pragma unroll
        for (int i = 0; i < 9; ++i) dst[t + i * NTHREADS] = src[t + i * NTHREADS];
    }
    ((float4*)sW2)[t & 511] = ((const float4*)g_W2i)[t & 511];  // 512 float4 (all threads, dup-safe)
    if (t < 128) sB1[t] = g_B1f[t];
    if (t < 16)  sB2[t] = b2g[t];

    // ---- stage x tile (with zero halo) ----
    for (int idx = t; idx < 16 * 18 * 10; idx += NTHREADS) {
        int c = idx / 180;
        int rem = idx - c * 180;
        int hh = rem / 10;
        int ww = rem - hh * 10;
        int h = h0 + hh - 1, w = w0 + ww - 1;
        float v = 0.f;
        if ((unsigned)h < 128u && (unsigned)w < 128u)
            v = x[((b * 16 + c) << 14) + (h << 7) + w];
        sX[idx] = v;
    }
    __syncthreads();

    const int chunk = t & 3;       // hidden-channel chunk (lanes 4q..4q+3 share a pixel)
    const int pix = t >> 2;        // 0..127
    const int th = pix & 15;
    const int tw = pix >> 4;
    const int c0 = chunk * 32;

    // ---- fused conv: 32 hidden accumulators as 16 packed f32x2 ----
    unsigned long long acc[16];
#pragma unroll
    for (int mm = 0; mm < 8; ++mm) {
        float4 bv = *(const float4*)(sB1 + c0 + mm * 4);
        acc[2 * mm]     = pack2(bv.x, bv.y);
        acc[2 * mm + 1] = pack2(bv.z, bv.w);
    }

    const float* wfbase = sWF + chunk * 4;
#pragma unroll 1
    for (int i = 0; i < 16; ++i) {
        const float* xrow = sX + i * 180 + th * 10 + tw;
        const float* wfi = wfbase + i * (9 * 128);
#pragma unroll
        for (int kh = 0; kh < 3; ++kh) {
#pragma unroll
            for (int kw = 0; kw < 3; ++kw) {
                float xs = xrow[kh * 10 + kw];
                unsigned long long xv;
                unsigned int xu = __float_as_uint(xs);
                asm("mov.b64 %0, {%1, %1};" : "=l"(xv) : "r"(xu));
                const float* wf = wfi + (kh * 3 + kw) * 128;
#pragma unroll
                for (int mm = 0; mm < 8; ++mm) {
                    ulonglong2 w2 = *(const ulonglong2*)(wf + mm * 16);
                    acc[2 * mm]     = fma2(w2.x, xv, acc[2 * mm]);
                    acc[2 * mm + 1] = fma2(w2.y, xv, acc[2 * mm + 1]);
                }
            }
        }
    }

    // ---- tail GEMM: out[o] partial = sum over my 32 hidden of W2[o,m]*relu(h[m]) ----
    float s[16];
#pragma unroll
    for (int o = 0; o < 16; ++o) s[o] = 0.f;

#pragma unroll 1
    for (int p = 0; p < 16; ++p) {
        unsigned int ia, ib;
        asm("mov.b64 {%0, %1}, %2;" : "=r"(ia), "=r"(ib) : "l"(acc[p]));
        float ha = fmaxf(__uint_as_float(ia), 0.f);
        float hb = fmaxf(__uint_as_float(ib), 0.f);
        const float* w2p = sW2 + chunk * 4 + (p >> 1) * 16 + (p & 1) * 2;
#pragma unroll
        for (int o = 0; o < 16; ++o) {
            float2 wv = *(const float2*)(w2p + o * 128);
            s[o] += wv.x * ha + wv.y * hb;
        }
    }

    // ---- quad reduction over the 4 chunks (lanes 4q..4q+3) ----
#pragma unroll
    for (int o = 0; o < 16; ++o) {
        s[o] += __shfl_xor_sync(0xFFFFFFFFu, s[o], 1);
        s[o] += __shfl_xor_sync(0xFFFFFFFFu, s[o], 2);
    }

    // each lane writes its 4 outputs: o in [chunk*4, chunk*4+4)
    float r0, r1, r2, r3;
    if (chunk == 0)      { r0 = s[0];  r1 = s[1];  r2 = s[2];  r3 = s[3];  }
    else if (chunk == 1) { r0 = s[4];  r1 = s[5];  r2 = s[6];  r3 = s[7];  }
    else if (chunk == 2) { r0 = s[8];  r1 = s[9];  r2 = s[10]; r3 = s[11]; }
    else                 { r0 = s[12]; r1 = s[13]; r2 = s[14]; r3 = s[15]; }

    const int ob = chunk * 4;
    r0 += sB2[ob + 0];
    r1 += sB2[ob + 1];
    r2 += sB2[ob + 2];
    r3 += sB2[ob + 3];

    const int w = w0 + tw, h = h0 + th;
    int off = ((((b << 7) + w) << 7) + h) * 16 + ob;   // out[b][w][h][o]
    float4 ov = make_float4(r0, r1, r2, r3);
    *(float4*)(out + off) = ov;
}

extern "C" void kernel_launch(void* const* d_in, const int* in_sizes, int n_in,
                              void* d_out, int out_size) {
    const float* x  = (const float*)d_in[0];
    const float* Wx = (const float*)d_in[1];
    const float* bx = (const float*)d_in[2];
    const float* Wy = (const float*)d_in[3];
    const float* by = (const float*)d_in[4];
    const float* W1 = (const float*)d_in[5];
    const float* b1 = (const float*)d_in[6];
    const float* W2 = (const float*)d_in[7];
    const float* b2 = (const float*)d_in[8];
    float* out = (float*)d_out;

    prep_wf_kernel<<<72, 256>>>(Wx, Wy, W1);
    prep_misc_kernel<<<8, 256>>>(W1, b1, bx, by, W2);

    cudaFuncSetAttribute(nca_main_kernel,
                         cudaFuncAttributeMaxDynamicSharedMemorySize, SMEM_BYTES);
    nca_main_kernel<<<32 * 128, NTHREADS, SMEM_BYTES>>>(x, b2, out);
}

// round 3
// speedup vs baseline: 3.3782x; 3.3782x over previous
#include <cuda_runtime.h>
#include <cuda_bf16.h>
#include <cstdint>

// ============================================================================
// out[b,w,h,o] = W2 @ relu( patch(x)[p,144] x WF[144,128] + b1f ) + b2
// mma.sync m16n8k16 bf16 (baseline PTX, works at .target sm_103),
// 2-term bf16 split -> 3 cross-term MMAs for ~fp32 accuracy.
// Tile: M=128 pixels (one (b,h) row over w), K=144, N=128 hidden.
// ============================================================================

#define NTHREADS 256
#define TILES_PER_BLOCK 4
#define NBLOCKS 1024

// ---- dynamic SMEM byte offsets ----
#define A_STRIDE_B 304                   // 152 bf16 per row
#define SB_BHI   0                       // B_hi [n=128][152] bf16 = 38912 B
#define SB_BLO   38912
#define SB_AHI   77824                   // A_hi [p=128][152] bf16 (h overlay)
#define SB_ALO   116736
#define SB_X     155648                  // x tile [16][3][132] f32 = 25344 B
#define SB_W2T   180992                  // W2T [m=128][16] f32 = 8192 B
#define SB_B1    189184                  // 128 f32
#define SB_B2    189696                  // 16 f32
#define SMEM_BYTES 189824
#define SB_H     SB_AHI                  // h [m=128][132] f32 = 67584 B overlay
#define H_STRIDE 132

// weights prepacked by prep kernels (device globals are zero-initialized)
__device__ __nv_bfloat16 g_Bhi[128 * 152];
__device__ __nv_bfloat16 g_Blo[128 * 152];
__device__ float g_W2T[2048];
__device__ float g_B1f[128];

// ---------------------------------------------------------------------------
__device__ __forceinline__ uint32_t smem_u32(const void* p) {
    uint32_t a;
    asm("{ .reg .u64 t; cvta.to.shared.u64 t, %1; cvt.u32.u64 %0, t; }" : "=r"(a) : "l"(p));
    return a;
}
__device__ __forceinline__ void ldsm_x4(uint32_t* r, uint32_t addr) {
    asm volatile("ldmatrix.sync.aligned.m8n8.x4.shared.b16 {%0,%1,%2,%3}, [%4];"
                 : "=r"(r[0]), "=r"(r[1]), "=r"(r[2]), "=r"(r[3]) : "r"(addr));
}
__device__ __forceinline__ void mma_bf16(float* c, const uint32_t* a, const uint32_t* b) {
    asm volatile("mma.sync.aligned.m16n8k16.row.col.f32.bf16.bf16.f32 "
                 "{%0,%1,%2,%3}, {%4,%5,%6,%7}, {%8,%9}, {%0,%1,%2,%3};"
                 : "+f"(c[0]), "+f"(c[1]), "+f"(c[2]), "+f"(c[3])
                 : "r"(a[0]), "r"(a[1]), "r"(a[2]), "r"(a[3]), "r"(b[0]), "r"(b[1]));
}
__device__ __forceinline__ uint32_t cvt_bf16x2(float hi, float lo) {
    uint32_t r;
    asm("cvt.rn.bf16x2.f32 %0, %1, %2;" : "=r"(r) : "f"(hi), "f"(lo));
    return r;
}
__device__ __forceinline__ unsigned long long fma2(unsigned long long a,
                                                   unsigned long long b,
                                                   unsigned long long c) {
    unsigned long long d;
    asm("fma.rn.f32x2 %0, %1, %2, %3;" : "=l"(d) : "l"(a), "l"(b), "l"(c));
    return d;
}

// ---------------------------------------------------------------------------
// prep: fused conv weights -> bf16 hi/lo, layout [n=hidden m][k], stride 152
// ---------------------------------------------------------------------------
__global__ void prep_b_kernel(const float* __restrict__ Wx,
                              const float* __restrict__ Wy,
                              const float* __restrict__ W1) {
    int idx = blockIdx.x * blockDim.x + threadIdx.x;
    if (idx >= 128 * 144) return;
    int m = idx / 144, k = idx - m * 144;
    int i = k / 9, kk = k - i * 9;
    const float* w1r = W1 + m * 48;
    float f = 0.f;
#pragma unroll
    for (int o = 0; o < 16; ++o) {
        f += w1r[o]      * Wx[(o * 16 + i) * 9 + kk];
        f += w1r[16 + o] * Wy[(o * 16 + i) * 9 + kk];
    }
    if (kk == 4) f += w1r[32 + i];
    __nv_bfloat16 hi = __float2bfloat16(f);
    __nv_bfloat16 lo = __float2bfloat16(f - __bfloat162float(hi));
    g_Bhi[m * 152 + k] = hi;
    g_Blo[m * 152 + k] = lo;
}

__global__ void prep_misc_kernel(const float* __restrict__ W1,
                                 const float* __restrict__ b1,
                                 const float* __restrict__ bx,
                                 const float* __restrict__ by,
                                 const float* __restrict__ W2) {
    int idx = blockIdx.x * blockDim.x + threadIdx.x;
    if (idx < 2048) {
        int m = idx >> 4, o = idx & 15;
        g_W2T[idx] = W2[o * 128 + m];
    }
    if (idx < 128) {
        float s = b1[idx];
        const float* w1r = W1 + idx * 48;
#pragma unroll
        for (int o = 0; o < 16; ++o) s += w1r[o] * bx[o] + w1r[16 + o] * by[o];
        g_B1f[idx] = s;
    }
}

// ---------------------------------------------------------------------------
__global__ __launch_bounds__(NTHREADS)
void nca_mma_kernel(const float* __restrict__ x,
                    const float* __restrict__ b2g,
                    float* __restrict__ out) {
    extern __shared__ char sm[];
    float* smf = (float*)sm;
    const uint32_t smem_base = smem_u32(sm);
    const int tid = threadIdx.x;
    const int wid = tid >> 5;
    const int lane = tid & 31;
    const int mw = wid & 1;    // M-warp (64-pixel strip)
    const int nw = wid >> 1;   // N-warp (32-hidden strip)

    // ---- stage persistent weights ----
    {
        const uint4* gh = (const uint4*)g_Bhi;
        const uint4* gl = (const uint4*)g_Blo;
        uint4* shh = (uint4*)(sm + SB_BHI);
        uint4* shl = (uint4*)(sm + SB_BLO);
        for (int i = tid; i < 2432; i += NTHREADS) { shh[i] = gh[i]; shl[i] = gl[i]; }
        uint4* w2 = (uint4*)(sm + SB_W2T);
        const uint4* gw2 = (const uint4*)g_W2T;
        for (int i = tid; i < 512; i += NTHREADS) w2[i] = gw2[i];
        if (tid < 128) smf[SB_B1 / 4 + tid] = g_B1f[tid];
        if (tid < 16)  smf[SB_B2 / 4 + tid] = b2g[tid];
    }

    const int p_build = tid & 127;            // pixel for A-build
    const int kbase = (tid >> 7) * 72;        // k half

    for (int j = 0; j < TILES_PER_BLOCK; ++j) {
        const int tile = blockIdx.x * TILES_PER_BLOCK + j;
        const int b = tile >> 7;
        const int h = tile & 127;

        __syncthreads();  // prev tile fully consumed (also covers weight staging)

        // ---- stage x rows h-1..h+1 into [16][3][132], w' = ww-1, zero halo ----
        for (int idx = tid; idx < 16 * 3 * 132; idx += NTHREADS) {
            int c = idx / 396;
            int rem = idx - c * 396;
            int r = rem / 132;
            int ww = rem - r * 132;
            int hh = h + r - 1, wg = ww - 1;
            float v = 0.f;
            if ((unsigned)hh < 128u && (unsigned)wg < 128u)
                v = x[((b * 16 + c) << 14) + (hh << 7) + wg];
            smf[SB_X / 4 + idx] = v;
        }
        __syncthreads();

        // ---- build A_hi/A_lo [p][k] bf16: row p, 72 k's per thread ----
        {
            const float* xp = smf + SB_X / 4 + p_build;
            char* arow_hi = sm + SB_AHI + p_build * A_STRIDE_B + kbase * 2;
            char* arow_lo = sm + SB_ALO + p_build * A_STRIDE_B + kbase * 2;
#pragma unroll
            for (int g = 0; g < 9; ++g) {
                uint32_t hi4[4], lo4[4];
#pragma unroll
                for (int u = 0; u < 4; ++u) {
                    int k0 = kbase + g * 8 + 2 * u;
                    int i0 = k0 / 9, t0 = k0 - 9 * i0;
                    int i1 = (k0 + 1) / 9, t1 = (k0 + 1) - 9 * i1;
                    float v0 = xp[i0 * 396 + (t0 / 3) * 132 + (t0 % 3)];
                    float v1 = xp[i1 * 396 + (t1 / 3) * 132 + (t1 % 3)];
                    uint32_t hp = cvt_bf16x2(v1, v0);
                    float f0 = __uint_as_float(hp << 16);
                    float f1 = __uint_as_float(hp & 0xFFFF0000u);
                    hi4[u] = hp;
                    lo4[u] = cvt_bf16x2(v1 - f1, v0 - f0);
                }
                *(uint4*)(arow_hi + g * 16) = make_uint4(hi4[0], hi4[1], hi4[2], hi4[3]);
                *(uint4*)(arow_lo + g * 16) = make_uint4(lo4[0], lo4[1], lo4[2], lo4[3]);
            }
        }
        __syncthreads();

        // ---- GEMM: acc[4mt][4nt] (M64 x N32 per warp), 9 K-steps, 3 terms ----
        float acc[4][4][4];
#pragma unroll
        for (int a = 0; a < 4; ++a)
#pragma unroll
            for (int bq = 0; bq < 4; ++bq)
#pragma unroll
                for (int e = 0; e < 4; ++e) acc[a][bq][e] = 0.f;

        const uint32_t a_row0 = (uint32_t)(mw * 64 + (lane & 7) + ((lane >> 3) & 1) * 8);
        const uint32_t a_coff = (uint32_t)((lane >> 4) * 16);
        const uint32_t b_row0 = (uint32_t)(nw * 32 + (lane & 7) + (lane >> 4) * 8);
        const uint32_t b_koff = (uint32_t)(((lane >> 3) & 1) * 16);

#pragma unroll 1
        for (int ks = 0; ks < 9; ++ks) {
            const uint32_t k0b = (uint32_t)(ks * 32);
            uint32_t ah[4][4], al[4][4], bh[2][4], bl[2][4];
#pragma unroll
            for (int mt = 0; mt < 4; ++mt) {
                uint32_t addr = smem_base + SB_AHI + (a_row0 + mt * 16) * A_STRIDE_B + k0b + a_coff;
                ldsm_x4(ah[mt], addr);
                ldsm_x4(al[mt], addr + (SB_ALO - SB_AHI));
            }
#pragma unroll
            for (int nt2 = 0; nt2 < 2; ++nt2) {
                uint32_t addr = smem_base + SB_BHI + (b_row0 + nt2 * 16) * A_STRIDE_B + k0b + b_koff;
                ldsm_x4(bh[nt2], addr);
                ldsm_x4(bl[nt2], addr + (SB_BLO - SB_BHI));
            }
#pragma unroll
            for (int mt = 0; mt < 4; ++mt)
#pragma unroll
                for (int nt = 0; nt < 4; ++nt) {
                    const uint32_t* bhp = &bh[nt >> 1][(nt & 1) * 2];
                    const uint32_t* blp = &bl[nt >> 1][(nt & 1) * 2];
                    mma_bf16(acc[mt][nt], ah[mt], bhp);
                    mma_bf16(acc[mt][nt], al[mt], bhp);
                    mma_bf16(acc[mt][nt], ah[mt], blp);
                }
        }
        __syncthreads();  // all warps done reading A before h overlay

        // ---- bias + relu -> h[m][132+p] (overlays A) ----
#pragma unroll
        for (int mt = 0; mt < 4; ++mt)
#pragma unroll
            for (int nt = 0; nt < 4; ++nt)
#pragma unroll
                for (int e = 0; e < 4; ++e) {
                    int pl = mw * 64 + mt * 16 + (lane >> 2) + (e >> 1) * 8;
                    int ml = nw * 32 + nt * 8 + (lane & 3) * 2 + (e & 1);
                    float v = fmaxf(acc[mt][nt][e] + smf[SB_B1 / 4 + ml], 0.f);
                    smf[SB_H / 4 + ml * H_STRIDE + pl] = v;
                }
        __syncthreads();

        // ---- tail: out[p][16] = h[p][:] @ W2T, split 64 m per lane pair ----
        {
            const int p = tid >> 1;
            const int m0 = (tid & 1) * 64;
            unsigned long long sa[8];
#pragma unroll
            for (int q = 0; q < 8; ++q) sa[q] = 0ull;
            const float* hp = smf + SB_H / 4 + m0 * H_STRIDE + p;
            const char* w2p = sm + SB_W2T + m0 * 64;
#pragma unroll 8
            for (int m = 0; m < 64; ++m) {
                float hv = hp[m * H_STRIDE];
                unsigned long long hv2;
                unsigned int hu = __float_as_uint(hv);
                asm("mov.b64 %0, {%1, %1};" : "=l"(hv2) : "r"(hu));
                const ulonglong2* wp = (const ulonglong2*)(w2p + m * 64);
                ulonglong2 wa = wp[0], wb = wp[1];
                sa[0] = fma2(wa.x, hv2, sa[0]);
                sa[1] = fma2(wa.y, hv2, sa[1]);
                sa[2] = fma2(wb.x, hv2, sa[2]);
                sa[3] = fma2(wb.y, hv2, sa[3]);
                ulonglong2 wc = wp[2], wd = wp[3];
                sa[4] = fma2(wc.x, hv2, sa[4]);
                sa[5] = fma2(wc.y, hv2, sa[5]);
                sa[6] = fma2(wd.x, hv2, sa[6]);
                sa[7] = fma2(wd.y, hv2, sa[7]);
            }
            float r[16];
#pragma unroll
            for (int q = 0; q < 8; ++q) {
                unsigned int lo, hi;
                asm("mov.b64 {%0, %1}, %2;" : "=r"(lo), "=r"(hi) : "l"(sa[q]));
                r[2 * q] = __uint_as_float(lo);
                r[2 * q + 1] = __uint_as_float(hi);
            }
#pragma unroll
            for (int o = 0; o < 16; ++o)
                r[o] += __shfl_xor_sync(0xFFFFFFFFu, r[o], 1);

            const int ob = (tid & 1) * 8;
            float4 o0 = make_float4(r[ob + 0] + smf[SB_B2 / 4 + ob + 0],
                                    r[ob + 1] + smf[SB_B2 / 4 + ob + 1],
                                    r[ob + 2] + smf[SB_B2 / 4 + ob + 2],
                                    r[ob + 3] + smf[SB_B2 / 4 + ob + 3]);
            float4 o1 = make_float4(r[ob + 4] + smf[SB_B2 / 4 + ob + 4],
                                    r[ob + 5] + smf[SB_B2 / 4 + ob + 5],
                                    r[ob + 6] + smf[SB_B2 / 4 + ob + 6],
                                    r[ob + 7] + smf[SB_B2 / 4 + ob + 7]);
            float4* op = (float4*)(out + ((((b << 7) + p) << 7) + h) * 16 + ob);
            op[0] = o0;
            op[1] = o1;
        }
    }
}

extern "C" void kernel_launch(void* const* d_in, const int* in_sizes, int n_in,
                              void* d_out, int out_size) {
    const float* x  = (const float*)d_in[0];
    const float* Wx = (const float*)d_in[1];
    const float* bx = (const float*)d_in[2];
    const float* Wy = (const float*)d_in[3];
    const float* by = (const float*)d_in[4];
    const float* W1 = (const float*)d_in[5];
    const float* b1 = (const float*)d_in[6];
    const float* W2 = (const float*)d_in[7];
    const float* b2 = (const float*)d_in[8];
    float* out = (float*)d_out;

    prep_b_kernel<<<72, 256>>>(Wx, Wy, W1);
    prep_misc_kernel<<<8, 256>>>(W1, b1, bx, by, W2);

    cudaFuncSetAttribute(nca_mma_kernel,
                         cudaFuncAttributeMaxDynamicSharedMemorySize, SMEM_BYTES);
    nca_mma_kernel<<<NBLOCKS, NTHREADS, SMEM_BYTES>>>(x, b2, out);
}

// round 4
// speedup vs baseline: 5.2892x; 1.5657x over previous
#include <cuda_runtime.h>
#include <cuda_bf16.h>
#include <cstdint>

// ============================================================================
// out[b,w,h,o] = W2 @ relu( patch(x)[p,144] x WF[144,128] + b1f ) + b2
// mma.sync m16n8k16 bf16 (baseline PTX), 2-term split, 3 cross-term MMAs.
// Warp layout: 8 warps x (M16 pixels, full N=128). Tail 128->16 GEMM done on
// tensor cores via in-register C->A fragment repack (no h SMEM roundtrip).
// ============================================================================

#define NTHREADS 256
#define TILES_PER_BLOCK 4
#define NBLOCKS 1024

#define A_STRIDE_B 304                   // 152 bf16 per row (conflict-free ldsm)
#define SB_BHI   0                       // [128][152] bf16
#define SB_BLO   38912
#define SB_AHI   77824                   // [128][152] bf16
#define SB_ALO   116736
#define SB_X     155648                  // [16][3][132] f32
#define SB_W2H   180992                  // [16][152] bf16
#define SB_W2L   185856
#define SB_B1    190720                  // 128 f32
#define SB_B2    191232                  // 16 f32
#define SB_OUT   191296                  // [128][20] f32 store-stage
#define SMEM_BYTES 201536

__device__ __nv_bfloat16 g_Bhi[128 * 152];
__device__ __nv_bfloat16 g_Blo[128 * 152];
__device__ __nv_bfloat16 g_W2h[16 * 152];
__device__ __nv_bfloat16 g_W2l[16 * 152];
__device__ float g_B1f[128];

// ---------------------------------------------------------------------------
__device__ __forceinline__ uint32_t smem_u32(const void* p) {
    uint32_t a;
    asm("{ .reg .u64 t; cvta.to.shared.u64 t, %1; cvt.u32.u64 %0, t; }" : "=r"(a) : "l"(p));
    return a;
}
__device__ __forceinline__ void ldsm_x4(uint32_t* r, uint32_t addr) {
    asm volatile("ldmatrix.sync.aligned.m8n8.x4.shared.b16 {%0,%1,%2,%3}, [%4];"
                 : "=r"(r[0]), "=r"(r[1]), "=r"(r[2]), "=r"(r[3]) : "r"(addr));
}
__device__ __forceinline__ void mma_bf16(float* c, const uint32_t* a, const uint32_t* b) {
    asm volatile("mma.sync.aligned.m16n8k16.row.col.f32.bf16.bf16.f32 "
                 "{%0,%1,%2,%3}, {%4,%5,%6,%7}, {%8,%9}, {%0,%1,%2,%3};"
                 : "+f"(c[0]), "+f"(c[1]), "+f"(c[2]), "+f"(c[3])
                 : "r"(a[0]), "r"(a[1]), "r"(a[2]), "r"(a[3]), "r"(b[0]), "r"(b[1]));
}
__device__ __forceinline__ uint32_t cvt_bf16x2(float hi, float lo) {
    uint32_t r;
    asm("cvt.rn.bf16x2.f32 %0, %1, %2;" : "=r"(r) : "f"(hi), "f"(lo));
    return r;
}

// ---------------------------------------------------------------------------
__global__ void prep_b_kernel(const float* __restrict__ Wx,
                              const float* __restrict__ Wy,
                              const float* __restrict__ W1) {
    int idx = blockIdx.x * blockDim.x + threadIdx.x;
    if (idx >= 128 * 144) return;
    int m = idx / 144, k = idx - m * 144;
    int i = k / 9, kk = k - i * 9;
    const float* w1r = W1 + m * 48;
    float f = 0.f;
#pragma unroll
    for (int o = 0; o < 16; ++o) {
        f += w1r[o]      * Wx[(o * 16 + i) * 9 + kk];
        f += w1r[16 + o] * Wy[(o * 16 + i) * 9 + kk];
    }
    if (kk == 4) f += w1r[32 + i];
    __nv_bfloat16 hi = __float2bfloat16(f);
    __nv_bfloat16 lo = __float2bfloat16(f - __bfloat162float(hi));
    g_Bhi[m * 152 + k] = hi;
    g_Blo[m * 152 + k] = lo;
}

__global__ void prep_misc_kernel(const float* __restrict__ W1,
                                 const float* __restrict__ b1,
                                 const float* __restrict__ bx,
                                 const float* __restrict__ by,
                                 const float* __restrict__ W2) {
    int idx = blockIdx.x * blockDim.x + threadIdx.x;
    if (idx < 2048) {
        int o = idx >> 7, m = idx & 127;
        float f = W2[o * 128 + m];
        __nv_bfloat16 hi = __float2bfloat16(f);
        __nv_bfloat16 lo = __float2bfloat16(f - __bfloat162float(hi));
        g_W2h[o * 152 + m] = hi;
        g_W2l[o * 152 + m] = lo;
    }
    if (idx < 128) {
        float s = b1[idx];
        const float* w1r = W1 + idx * 48;
#pragma unroll
        for (int o = 0; o < 16; ++o) s += w1r[o] * bx[o] + w1r[16 + o] * by[o];
        g_B1f[idx] = s;
    }
}

// ---------------------------------------------------------------------------
__global__ __launch_bounds__(NTHREADS)
void nca_mma_kernel(const float* __restrict__ x,
                    const float* __restrict__ b2g,
                    float* __restrict__ out) {
    extern __shared__ char sm[];
    float* smf = (float*)sm;
    const uint32_t smem_base = smem_u32(sm);
    const int tid = threadIdx.x;
    const int wid = tid >> 5;
    const int lane = tid & 31;
    const int q = lane & 3;

    // ---- stage persistent weights ----
    {
        const uint4* gh = (const uint4*)g_Bhi;
        const uint4* gl = (const uint4*)g_Blo;
        uint4* shh = (uint4*)(sm + SB_BHI);
        uint4* shl = (uint4*)(sm + SB_BLO);
        for (int i = tid; i < 2432; i += NTHREADS) { shh[i] = gh[i]; shl[i] = gl[i]; }
        uint4* w2h = (uint4*)(sm + SB_W2H);
        uint4* w2l = (uint4*)(sm + SB_W2L);
        const uint4* gw2h = (const uint4*)g_W2h;
        const uint4* gw2l = (const uint4*)g_W2l;
        for (int i = tid; i < 304; i += NTHREADS) { w2h[i] = gw2h[i]; w2l[i] = gw2l[i]; }
        if (tid < 128) smf[SB_B1 / 4 + tid] = g_B1f[tid];
        if (tid < 16)  smf[SB_B2 / 4 + tid] = b2g[tid];
    }

    const int p_build = tid & 127;
    const int kbase = (tid >> 7) * 72;

    // ldsm address components
    const uint32_t a_addr0 = smem_base + SB_AHI +
        (uint32_t)(wid * 16 + (lane & 7) + ((lane >> 3) & 1) * 8) * A_STRIDE_B +
        (uint32_t)((lane >> 4) * 16);
    const uint32_t b_row = (uint32_t)((lane & 7) + (lane >> 4) * 8);
    const uint32_t b_koff = (uint32_t)(((lane >> 3) & 1) * 16);
    const uint32_t b_addr0 = smem_base + SB_BHI + b_row * A_STRIDE_B + b_koff;
    const uint32_t w2_addr0 = smem_base + SB_W2H + b_row * A_STRIDE_B + b_koff;

    for (int j = 0; j < TILES_PER_BLOCK; ++j) {
        const int tile = blockIdx.x * TILES_PER_BLOCK + j;
        const int b = tile >> 7;
        const int h = tile & 127;

        __syncthreads();  // prior tile fully consumed

        // ---- stage x rows h-1..h+1 -> [16][3][132], zero halo ----
        for (int idx = tid; idx < 16 * 3 * 132; idx += NTHREADS) {
            int c = idx / 396;
            int rem = idx - c * 396;
            int r = rem / 132;
            int ww = rem - r * 132;
            int hh = h + r - 1, wg = ww - 1;
            float v = 0.f;
            if ((unsigned)hh < 128u && (unsigned)wg < 128u)
                v = x[((b * 16 + c) << 14) + (hh << 7) + wg];
            smf[SB_X / 4 + idx] = v;
        }
        __syncthreads();

        // ---- build A_hi/A_lo [p][k] bf16 ----
        {
            const float* xp = smf + SB_X / 4 + p_build;
            char* arow_hi = sm + SB_AHI + p_build * A_STRIDE_B + kbase * 2;
            char* arow_lo = sm + SB_ALO + p_build * A_STRIDE_B + kbase * 2;
#pragma unroll
            for (int g = 0; g < 9; ++g) {
                uint32_t hi4[4], lo4[4];
#pragma unroll
                for (int u = 0; u < 4; ++u) {
                    int k0 = kbase + g * 8 + 2 * u;
                    int i0 = k0 / 9, t0 = k0 - 9 * i0;
                    int i1 = (k0 + 1) / 9, t1 = (k0 + 1) - 9 * i1;
                    float v0 = xp[i0 * 396 + (t0 / 3) * 132 + (t0 % 3)];
                    float v1 = xp[i1 * 396 + (t1 / 3) * 132 + (t1 % 3)];
                    uint32_t hp = cvt_bf16x2(v1, v0);
                    float f0 = __uint_as_float(hp << 16);
                    float f1 = __uint_as_float(hp & 0xFFFF0000u);
                    hi4[u] = hp;
                    lo4[u] = cvt_bf16x2(v1 - f1, v0 - f0);
                }
                *(uint4*)(arow_hi + g * 16) = make_uint4(hi4[0], hi4[1], hi4[2], hi4[3]);
                *(uint4*)(arow_lo + g * 16) = make_uint4(lo4[0], lo4[1], lo4[2], lo4[3]);
            }
        }
        __syncthreads();

        // ---- main GEMM: per warp M16 x N128 x K144, acc init = b1 ----
        float acc[16][4];
#pragma unroll
        for (int nt = 0; nt < 16; ++nt) {
            float2 bv = *(const float2*)(smf + SB_B1 / 4 + nt * 8 + q * 2);
            acc[nt][0] = bv.x; acc[nt][1] = bv.y;
            acc[nt][2] = bv.x; acc[nt][3] = bv.y;
        }

#pragma unroll 1
        for (int ks = 0; ks < 9; ++ks) {
            const uint32_t kb = (uint32_t)(ks * 32);
            uint32_t ah[4], al[4];
            ldsm_x4(ah, a_addr0 + kb);
            ldsm_x4(al, a_addr0 + kb + (SB_ALO - SB_AHI));
#pragma unroll
            for (int nt2 = 0; nt2 < 8; ++nt2) {
                uint32_t bh[4], bl[4];
                uint32_t baddr = b_addr0 + (uint32_t)(nt2 * 16) * A_STRIDE_B + kb;
                ldsm_x4(bh, baddr);
                ldsm_x4(bl, baddr + (SB_BLO - SB_BHI));
                mma_bf16(acc[2 * nt2],     ah, &bh[0]);
                mma_bf16(acc[2 * nt2 + 1], ah, &bh[2]);
                mma_bf16(acc[2 * nt2],     al, &bh[0]);
                mma_bf16(acc[2 * nt2 + 1], al, &bh[2]);
                mma_bf16(acc[2 * nt2],     ah, &bl[0]);
                mma_bf16(acc[2 * nt2 + 1], ah, &bl[2]);
            }
        }

        // ---- tail GEMM: out16 = relu(h) @ W2T, acc init = b2 ----
        float oacc[2][4];
        {
            float2 b2a = *(const float2*)(smf + SB_B2 / 4 + q * 2);
            float2 b2b = *(const float2*)(smf + SB_B2 / 4 + 8 + q * 2);
            oacc[0][0] = b2a.x; oacc[0][1] = b2a.y; oacc[0][2] = b2a.x; oacc[0][3] = b2a.y;
            oacc[1][0] = b2b.x; oacc[1][1] = b2b.y; oacc[1][2] = b2b.x; oacc[1][3] = b2b.y;
        }

#pragma unroll
        for (int kt = 0; kt < 8; ++kt) {
            // repack relu(acc[2kt]), relu(acc[2kt+1]) -> A fragment (hi/lo split)
            float y0 = fmaxf(acc[2 * kt][0], 0.f),     y1 = fmaxf(acc[2 * kt][1], 0.f);
            float y2 = fmaxf(acc[2 * kt][2], 0.f),     y3 = fmaxf(acc[2 * kt][3], 0.f);
            float z0 = fmaxf(acc[2 * kt + 1][0], 0.f), z1 = fmaxf(acc[2 * kt + 1][1], 0.f);
            float z2 = fmaxf(acc[2 * kt + 1][2], 0.f), z3 = fmaxf(acc[2 * kt + 1][3], 0.f);
            uint32_t ah2[4], al2[4];
            ah2[0] = cvt_bf16x2(y1, y0);
            ah2[1] = cvt_bf16x2(y3, y2);
            ah2[2] = cvt_bf16x2(z1, z0);
            ah2[3] = cvt_bf16x2(z3, z2);
            al2[0] = cvt_bf16x2(y1 - __uint_as_float(ah2[0] & 0xFFFF0000u),
                                y0 - __uint_as_float(ah2[0] << 16));
            al2[1] = cvt_bf16x2(y3 - __uint_as_float(ah2[1] & 0xFFFF0000u),
                                y2 - __uint_as_float(ah2[1] << 16));
            al2[2] = cvt_bf16x2(z1 - __uint_as_float(ah2[2] & 0xFFFF0000u),
                                z0 - __uint_as_float(ah2[2] << 16));
            al2[3] = cvt_bf16x2(z3 - __uint_as_float(ah2[3] & 0xFFFF0000u),
                                z2 - __uint_as_float(ah2[3] << 16));

            uint32_t wh[4], wl[4];
            uint32_t waddr = w2_addr0 + (uint32_t)(kt * 32);
            ldsm_x4(wh, waddr);
            ldsm_x4(wl, waddr + (SB_W2L - SB_W2H));
            mma_bf16(oacc[0], ah2, &wh[0]);
            mma_bf16(oacc[1], ah2, &wh[2]);
            mma_bf16(oacc[0], al2, &wh[0]);
            mma_bf16(oacc[1], al2, &wh[2]);
            mma_bf16(oacc[0], ah2, &wl[0]);
            mma_bf16(oacc[1], ah2, &wl[2]);
        }

        // ---- stage outputs in SMEM (stride 20 words) then coalesced STG ----
        {
            const int r = lane >> 2;
            float* s0 = smf + SB_OUT / 4 + (wid * 16 + r) * 20;
            float* s1 = smf + SB_OUT / 4 + (wid * 16 + r + 8) * 20;
            *(float2*)(s0 + 2 * q)     = make_float2(oacc[0][0], oacc[0][1]);
            *(float2*)(s0 + 8 + 2 * q) = make_float2(oacc[1][0], oacc[1][1]);
            *(float2*)(s1 + 2 * q)     = make_float2(oacc[0][2], oacc[0][3]);
            *(float2*)(s1 + 8 + 2 * q) = make_float2(oacc[1][2], oacc[1][3]);
        }
        __syncthreads();
        {
            const long ob = ((long)((b << 7)) << 11) + ((long)h << 4);
#pragma unroll
            for (int t = 0; t < 2; ++t) {
                int i = tid + t * NTHREADS;
                int p = i >> 2, q4 = (i & 3) * 4;
                float4 v = *(const float4*)(smf + SB_OUT / 4 + p * 20 + q4);
                *(float4*)(out + ob + ((long)p << 11) + q4) = v;
            }
        }
    }
}

extern "C" void kernel_launch(void* const* d_in, const int* in_sizes, int n_in,
                              void* d_out, int out_size) {
    const float* x  = (const float*)d_in[0];
    const float* Wx = (const float*)d_in[1];
    const float* bx = (const float*)d_in[2];
    const float* Wy = (const float*)d_in[3];
    const float* by = (const float*)d_in[4];
    const float* W1 = (const float*)d_in[5];
    const float* b1 = (const float*)d_in[6];
    const float* W2 = (const float*)d_in[7];
    const float* b2 = (const float*)d_in[8];
    float* out = (float*)d_out;

    prep_b_kernel<<<72, 256>>>(Wx, Wy, W1);
    prep_misc_kernel<<<8, 256>>>(W1, b1, bx, by, W2);

    cudaFuncSetAttribute(nca_mma_kernel,
                         cudaFuncAttributeMaxDynamicSharedMemorySize, SMEM_BYTES);
    nca_mma_kernel<<<NBLOCKS, NTHREADS, SMEM_BYTES>>>(x, b2, out);
}

// round 5
// speedup vs baseline: 5.4189x; 1.0245x over previous
#include <cuda_runtime.h>
#include <cuda_bf16.h>
#include <cstdint>

// ============================================================================
// out[b,w,h,o] = W2 @ relu( patch(x)[p,144] x WF[144,128] + b1f ) + b2
// mma.sync m16n8k16 bf16, 2-term split, 3 cross-term MMAs.
// Warp grid 4(M)x2(N): M32 x N64 per warp. Tail 128->16 GEMM on tensor cores
// with K split across the 2 N-warps; partials summed in the store pass.
// ============================================================================

#define NTHREADS 256
#define TILES_PER_BLOCK 4
#define NBLOCKS 1024

#define A_STRIDE_B 304                   // 152 bf16 per row
#define SB_BHI   0                       // [128][152] bf16
#define SB_BLO   38912
#define SB_AHI   77824
#define SB_ALO   116736
#define SB_X     155648                  // [16][3][132] f32
#define SB_W2H   180992                  // [16][152] bf16
#define SB_W2L   185856
#define SB_B1    190720                  // 128 f32
#define SB_B2    191232                  // 16 f32
#define SB_O0    191296                  // [128][20] f32 partial 0
#define SB_O1    201536                  // [128][20] f32 partial 1
#define SMEM_BYTES 211776

__device__ __nv_bfloat16 g_Bhi[128 * 152];
__device__ __nv_bfloat16 g_Blo[128 * 152];
__device__ __nv_bfloat16 g_W2h[16 * 152];
__device__ __nv_bfloat16 g_W2l[16 * 152];
__device__ float g_B1f[128];

// ---------------------------------------------------------------------------
__device__ __forceinline__ uint32_t smem_u32(const void* p) {
    uint32_t a;
    asm("{ .reg .u64 t; cvta.to.shared.u64 t, %1; cvt.u32.u64 %0, t; }" : "=r"(a) : "l"(p));
    return a;
}
__device__ __forceinline__ void ldsm_x4(uint32_t* r, uint32_t addr) {
    asm volatile("ldmatrix.sync.aligned.m8n8.x4.shared.b16 {%0,%1,%2,%3}, [%4];"
                 : "=r"(r[0]), "=r"(r[1]), "=r"(r[2]), "=r"(r[3]) : "r"(addr));
}
__device__ __forceinline__ void mma_bf16(float* c, const uint32_t* a, const uint32_t* b) {
    asm volatile("mma.sync.aligned.m16n8k16.row.col.f32.bf16.bf16.f32 "
                 "{%0,%1,%2,%3}, {%4,%5,%6,%7}, {%8,%9}, {%0,%1,%2,%3};"
                 : "+f"(c[0]), "+f"(c[1]), "+f"(c[2]), "+f"(c[3])
                 : "r"(a[0]), "r"(a[1]), "r"(a[2]), "r"(a[3]), "r"(b[0]), "r"(b[1]));
}
__device__ __forceinline__ uint32_t cvt_bf16x2(float hi, float lo) {
    uint32_t r;
    asm("cvt.rn.bf16x2.f32 %0, %1, %2;" : "=r"(r) : "f"(hi), "f"(lo));
    return r;
}

// ---------------------------------------------------------------------------
__global__ void prep_b_kernel(const float* __restrict__ Wx,
                              const float* __restrict__ Wy,
                              const float* __restrict__ W1) {
    int idx = blockIdx.x * blockDim.x + threadIdx.x;
    if (idx >= 128 * 144) return;
    int m = idx / 144, k = idx - m * 144;
    int i = k / 9, kk = k - i * 9;
    const float* w1r = W1 + m * 48;
    float f = 0.f;
#pragma unroll
    for (int o = 0; o < 16; ++o) {
        f += w1r[o]      * Wx[(o * 16 + i) * 9 + kk];
        f += w1r[16 + o] * Wy[(o * 16 + i) * 9 + kk];
    }
    if (kk == 4) f += w1r[32 + i];
    __nv_bfloat16 hi = __float2bfloat16(f);
    __nv_bfloat16 lo = __float2bfloat16(f - __bfloat162float(hi));
    g_Bhi[m * 152 + k] = hi;
    g_Blo[m * 152 + k] = lo;
}

__global__ void prep_misc_kernel(const float* __restrict__ W1,
                                 const float* __restrict__ b1,
                                 const float* __restrict__ bx,
                                 const float* __restrict__ by,
                                 const float* __restrict__ W2) {
    int idx = blockIdx.x * blockDim.x + threadIdx.x;
    if (idx < 2048) {
        int o = idx >> 7, m = idx & 127;
        float f = W2[o * 128 + m];
        __nv_bfloat16 hi = __float2bfloat16(f);
        __nv_bfloat16 lo = __float2bfloat16(f - __bfloat162float(hi));
        g_W2h[o * 152 + m] = hi;
        g_W2l[o * 152 + m] = lo;
    }
    if (idx < 128) {
        float s = b1[idx];
        const float* w1r = W1 + idx * 48;
#pragma unroll
        for (int o = 0; o < 16; ++o) s += w1r[o] * bx[o] + w1r[16 + o] * by[o];
        g_B1f[idx] = s;
    }
}

// ---------------------------------------------------------------------------
__global__ __launch_bounds__(NTHREADS)
void nca_mma_kernel(const float* __restrict__ x,
                    const float* __restrict__ b2g,
                    float* __restrict__ out) {
    extern __shared__ char sm[];
    float* smf = (float*)sm;
    const uint32_t smem_base = smem_u32(sm);
    const int tid = threadIdx.x;
    const int wid = tid >> 5;
    const int lane = tid & 31;
    const int q = lane & 3;
    const int mw = wid & 3;    // M-warp: pixels [mw*32, mw*32+32)
    const int nw = wid >> 2;   // N-warp: hidden [nw*64, nw*64+64)

    // ---- stage persistent weights ----
    {
        const uint4* gh = (const uint4*)g_Bhi;
        const uint4* gl = (const uint4*)g_Blo;
        uint4* shh = (uint4*)(sm + SB_BHI);
        uint4* shl = (uint4*)(sm + SB_BLO);
        for (int i = tid; i < 2432; i += NTHREADS) { shh[i] = gh[i]; shl[i] = gl[i]; }
        uint4* w2h = (uint4*)(sm + SB_W2H);
        uint4* w2l = (uint4*)(sm + SB_W2L);
        const uint4* gw2h = (const uint4*)g_W2h;
        const uint4* gw2l = (const uint4*)g_W2l;
        for (int i = tid; i < 304; i += NTHREADS) { w2h[i] = gw2h[i]; w2l[i] = gw2l[i]; }
        if (tid < 128) smf[SB_B1 / 4 + tid] = g_B1f[tid];
        if (tid < 16)  smf[SB_B2 / 4 + tid] = b2g[tid];
    }
    __syncthreads();

    // ---- hoist bias fragments into registers ----
    float bini[8][2];
#pragma unroll
    for (int nt = 0; nt < 8; ++nt) {
        bini[nt][0] = smf[SB_B1 / 4 + nw * 64 + nt * 8 + q * 2];
        bini[nt][1] = smf[SB_B1 / 4 + nw * 64 + nt * 8 + q * 2 + 1];
    }
    float b2i[2][2];
#pragma unroll
    for (int jj = 0; jj < 2; ++jj) {
        b2i[jj][0] = (nw == 0) ? smf[SB_B2 / 4 + jj * 8 + q * 2] : 0.f;
        b2i[jj][1] = (nw == 0) ? smf[SB_B2 / 4 + jj * 8 + q * 2 + 1] : 0.f;
    }

    const int p_build = tid & 127;
    const int kbase = (tid >> 7) * 72;

    // ldsm address components
    const uint32_t a_addr0 = smem_base + SB_AHI +
        (uint32_t)(mw * 32 + (lane & 7) + ((lane >> 3) & 1) * 8) * A_STRIDE_B +
        (uint32_t)((lane >> 4) * 16);
    const uint32_t b_addr0 = smem_base + SB_BHI +
        (uint32_t)(nw * 64 + (lane & 7) + (lane >> 4) * 8) * A_STRIDE_B +
        (uint32_t)(((lane >> 3) & 1) * 16);
    const uint32_t w2_addr0 = smem_base + SB_W2H +
        (uint32_t)((lane & 7) + (lane >> 4) * 8) * A_STRIDE_B +
        (uint32_t)(((lane >> 3) & 1) * 16) + (uint32_t)(nw * 128);

    for (int j = 0; j < TILES_PER_BLOCK; ++j) {
        const int tile = blockIdx.x * TILES_PER_BLOCK + j;
        const int b = tile >> 7;
        const int h = tile & 127;

        __syncthreads();  // prior tile fully consumed

        // ---- stage x rows h-1..h+1 -> [16][3][132], zero halo ----
        for (int idx = tid; idx < 16 * 3 * 132; idx += NTHREADS) {
            int c = idx / 396;
            int rem = idx - c * 396;
            int r = rem / 132;
            int ww = rem - r * 132;
            int hh = h + r - 1, wg = ww - 1;
            float v = 0.f;
            if ((unsigned)hh < 128u && (unsigned)wg < 128u)
                v = x[((b * 16 + c) << 14) + (hh << 7) + wg];
            smf[SB_X / 4 + idx] = v;
        }
        __syncthreads();

        // ---- build A_hi/A_lo [p][k] bf16 ----
        {
            const float* xp = smf + SB_X / 4 + p_build;
            char* arow_hi = sm + SB_AHI + p_build * A_STRIDE_B + kbase * 2;
            char* arow_lo = sm + SB_ALO + p_build * A_STRIDE_B + kbase * 2;
#pragma unroll
            for (int g = 0; g < 9; ++g) {
                uint32_t hi4[4], lo4[4];
#pragma unroll
                for (int u = 0; u < 4; ++u) {
                    int k0 = kbase + g * 8 + 2 * u;
                    int i0 = k0 / 9, t0 = k0 - 9 * i0;
                    int i1 = (k0 + 1) / 9, t1 = (k0 + 1) - 9 * i1;
                    float v0 = xp[i0 * 396 + (t0 / 3) * 132 + (t0 % 3)];
                    float v1 = xp[i1 * 396 + (t1 / 3) * 132 + (t1 % 3)];
                    uint32_t hp = cvt_bf16x2(v1, v0);
                    float f0 = __uint_as_float(hp << 16);
                    float f1 = __uint_as_float(hp & 0xFFFF0000u);
                    hi4[u] = hp;
                    lo4[u] = cvt_bf16x2(v1 - f1, v0 - f0);
                }
                *(uint4*)(arow_hi + g * 16) = make_uint4(hi4[0], hi4[1], hi4[2], hi4[3]);
                *(uint4*)(arow_lo + g * 16) = make_uint4(lo4[0], lo4[1], lo4[2], lo4[3]);
            }
        }
        __syncthreads();

        // ---- main GEMM: M32 x N64 x K144 per warp, acc init = b1 ----
        float acc[2][8][4];
#pragma unroll
        for (int mt = 0; mt < 2; ++mt)
#pragma unroll
            for (int nt = 0; nt < 8; ++nt) {
                acc[mt][nt][0] = bini[nt][0]; acc[mt][nt][1] = bini[nt][1];
                acc[mt][nt][2] = bini[nt][0]; acc[mt][nt][3] = bini[nt][1];
            }

#pragma unroll 1
        for (int ks = 0; ks < 9; ++ks) {
            const uint32_t kb = (uint32_t)(ks * 32);
            uint32_t ah[2][4], al[2][4];
#pragma unroll
            for (int mt = 0; mt < 2; ++mt) {
                uint32_t aa = a_addr0 + (uint32_t)(mt * 16) * A_STRIDE_B + kb;
                ldsm_x4(ah[mt], aa);
                ldsm_x4(al[mt], aa + (SB_ALO - SB_AHI));
            }
#pragma unroll
            for (int g = 0; g < 4; ++g) {
                uint32_t bh[4], bl[4];
                uint32_t ba = b_addr0 + (uint32_t)(g * 16) * A_STRIDE_B + kb;
                ldsm_x4(bh, ba);
                ldsm_x4(bl, ba + (SB_BLO - SB_BHI));
#pragma unroll
                for (int mt = 0; mt < 2; ++mt) {
                    mma_bf16(acc[mt][2 * g],     ah[mt], &bh[0]);
                    mma_bf16(acc[mt][2 * g + 1], ah[mt], &bh[2]);
                    mma_bf16(acc[mt][2 * g],     al[mt], &bh[0]);
                    mma_bf16(acc[mt][2 * g + 1], al[mt], &bh[2]);
                    mma_bf16(acc[mt][2 * g],     ah[mt], &bl[0]);
                    mma_bf16(acc[mt][2 * g + 1], ah[mt], &bl[2]);
                }
            }
        }

        // ---- tail GEMM over this warp's K=64 hidden half ----
        float oacc[2][2][4];
#pragma unroll
        for (int mt = 0; mt < 2; ++mt)
#pragma unroll
            for (int jj = 0; jj < 2; ++jj) {
                oacc[mt][jj][0] = b2i[jj][0]; oacc[mt][jj][1] = b2i[jj][1];
                oacc[mt][jj][2] = b2i[jj][0]; oacc[mt][jj][3] = b2i[jj][1];
            }

#pragma unroll
        for (int kt = 0; kt < 4; ++kt) {
            uint32_t wh[4], wl[4];
            uint32_t waddr = w2_addr0 + (uint32_t)(kt * 32);
            ldsm_x4(wh, waddr);
            ldsm_x4(wl, waddr + (SB_W2L - SB_W2H));
#pragma unroll
            for (int mt = 0; mt < 2; ++mt) {
                float y0 = fmaxf(acc[mt][2 * kt][0], 0.f),     y1 = fmaxf(acc[mt][2 * kt][1], 0.f);
                float y2 = fmaxf(acc[mt][2 * kt][2], 0.f),     y3 = fmaxf(acc[mt][2 * kt][3], 0.f);
                float z0 = fmaxf(acc[mt][2 * kt + 1][0], 0.f), z1 = fmaxf(acc[mt][2 * kt + 1][1], 0.f);
                float z2 = fmaxf(acc[mt][2 * kt + 1][2], 0.f), z3 = fmaxf(acc[mt][2 * kt + 1][3], 0.f);
                uint32_t ah2[4], al2[4];
                ah2[0] = cvt_bf16x2(y1, y0);
                ah2[1] = cvt_bf16x2(y3, y2);
                ah2[2] = cvt_bf16x2(z1, z0);
                ah2[3] = cvt_bf16x2(z3, z2);
                al2[0] = cvt_bf16x2(y1 - __uint_as_float(ah2[0] & 0xFFFF0000u),
                                    y0 - __uint_as_float(ah2[0] << 16));
                al2[1] = cvt_bf16x2(y3 - __uint_as_float(ah2[1] & 0xFFFF0000u),
                                    y2 - __uint_as_float(ah2[1] << 16));
                al2[2] = cvt_bf16x2(z1 - __uint_as_float(ah2[2] & 0xFFFF0000u),
                                    z0 - __uint_as_float(ah2[2] << 16));
                al2[3] = cvt_bf16x2(z3 - __uint_as_float(ah2[3] & 0xFFFF0000u),
                                    z2 - __uint_as_float(ah2[3] << 16));
                mma_bf16(oacc[mt][0], ah2, &wh[0]);
                mma_bf16(oacc[mt][1], ah2, &wh[2]);
                mma_bf16(oacc[mt][0], al2, &wh[0]);
                mma_bf16(oacc[mt][1], al2, &wh[2]);
                mma_bf16(oacc[mt][0], ah2, &wl[0]);
                mma_bf16(oacc[mt][1], ah2, &wl[2]);
            }
        }

        // ---- stage partial outputs (stride-20 pad), per-N-warp buffer ----
        {
            float* obuf = smf + (nw ? SB_O1 : SB_O0) / 4;
#pragma unroll
            for (int mt = 0; mt < 2; ++mt) {
                int p0 = mw * 32 + mt * 16 + (lane >> 2);
                float* s0 = obuf + p0 * 20;
                float* s1 = obuf + (p0 + 8) * 20;
                *(float2*)(s0 + 2 * q)     = make_float2(oacc[mt][0][0], oacc[mt][0][1]);
                *(float2*)(s0 + 8 + 2 * q) = make_float2(oacc[mt][1][0], oacc[mt][1][1]);
                *(float2*)(s1 + 2 * q)     = make_float2(oacc[mt][0][2], oacc[mt][0][3]);
                *(float2*)(s1 + 8 + 2 * q) = make_float2(oacc[mt][1][2], oacc[mt][1][3]);
            }
        }
        __syncthreads();

        // ---- sum partials + coalesced store ----
        {
            const long obase = ((long)((b << 7)) << 11) + ((long)h << 4);
#pragma unroll
            for (int t = 0; t < 2; ++t) {
                int i = tid + t * NTHREADS;
                int p = i >> 2, c4 = (i & 3) * 4;
                float4 v0 = *(const float4*)(smf + SB_O0 / 4 + p * 20 + c4);
                float4 v1 = *(const float4*)(smf + SB_O1 / 4 + p * 20 + c4);
                float4 v = make_float4(v0.x + v1.x, v0.y + v1.y, v0.z + v1.z, v0.w + v1.w);
                *(float4*)(out + obase + ((long)p << 11) + c4) = v;
            }
        }
    }
}

extern "C" void kernel_launch(void* const* d_in, const int* in_sizes, int n_in,
                              void* d_out, int out_size) {
    const float* x  = (const float*)d_in[0];
    const float* Wx = (const float*)d_in[1];
    const float* bx = (const float*)d_in[2];
    const float* Wy = (const float*)d_in[3];
    const float* by = (const float*)d_in[4];
    const float* W1 = (const float*)d_in[5];
    const float* b1 = (const float*)d_in[6];
    const float* W2 = (const float*)d_in[7];
    const float* b2 = (const float*)d_in[8];
    float* out = (float*)d_out;

    prep_b_kernel<<<72, 256>>>(Wx, Wy, W1);
    prep_misc_kernel<<<8, 256>>>(W1, b1, bx, by, W2);

    cudaFuncSetAttribute(nca_mma_kernel,
                         cudaFuncAttributeMaxDynamicSharedMemorySize, SMEM_BYTES);
    nca_mma_kernel<<<NBLOCKS, NTHREADS, SMEM_BYTES>>>(x, b2, out);
}

// round 7
// speedup vs baseline: 6.1108x; 1.1277x over previous
#include <cuda_runtime.h>
#include <cuda_bf16.h>
#include <cstdint>

// ============================================================================
// out[b,w,h,o] = W2 @ relu( patch(x)[p,144] x WF[144,128] + b1f ) + b2
// mma.sync m16n8k16 bf16, 2-term split, 3 cross-term MMAs.
// 512 threads: warp grid 8(M)x2(N), M16 x N64 per warp (4 warps/SMSP).
// cp.async double-buffered x prefetch overlaps GMEM latency with GEMM.
// ============================================================================

#define NTHREADS 512
#define TILES_PER_BLOCK 4
#define NBLOCKS 1024

#define A_STRIDE_B 304                   // 152 bf16 per row
#define SB_BHI   0                       // [128][152] bf16
#define SB_BLO   38912
#define SB_AHI   77824
#define SB_ALO   116736
#define SB_X0    155648                  // [16][3][132] f32 (buf 0)
#define SB_X1    180992                  // (buf 1)
#define SB_W2H   206336                  // [16][152] bf16
#define SB_W2L   211200
#define SB_B1    216064                  // 128 f32
#define SB_B2    216576                  // 16 f32
#define SMEM_BYTES 216640
// output staging overlays the CURRENT (dead) X buffer: 2 x 10240 B <= 25344 B

__device__ __nv_bfloat16 g_Bhi[128 * 152];
__device__ __nv_bfloat16 g_Blo[128 * 152];
__device__ __nv_bfloat16 g_W2h[16 * 152];
__device__ __nv_bfloat16 g_W2l[16 * 152];
__device__ float g_B1f[128];

// ---------------------------------------------------------------------------
__device__ __forceinline__ uint32_t smem_u32(const void* p) {
    uint32_t a;
    asm("{ .reg .u64 t; cvta.to.shared.u64 t, %1; cvt.u32.u64 %0, t; }" : "=r"(a) : "l"(p));
    return a;
}
__device__ __forceinline__ void ldsm_x4(uint32_t* r, uint32_t addr) {
    asm volatile("ldmatrix.sync.aligned.m8n8.x4.shared.b16 {%0,%1,%2,%3}, [%4];"
                 : "=r"(r[0]), "=r"(r[1]), "=r"(r[2]), "=r"(r[3]) : "r"(addr));
}
__device__ __forceinline__ void mma_bf16(float* c, const uint32_t* a, const uint32_t* b) {
    asm volatile("mma.sync.aligned.m16n8k16.row.col.f32.bf16.bf16.f32 "
                 "{%0,%1,%2,%3}, {%4,%5,%6,%7}, {%8,%9}, {%0,%1,%2,%3};"
                 : "+f"(c[0]), "+f"(c[1]), "+f"(c[2]), "+f"(c[3])
                 : "r"(a[0]), "r"(a[1]), "r"(a[2]), "r"(a[3]), "r"(b[0]), "r"(b[1]));
}
__device__ __forceinline__ uint32_t cvt_bf16x2(float hi, float lo) {
    uint32_t r;
    asm("cvt.rn.bf16x2.f32 %0, %1, %2;" : "=r"(r) : "f"(hi), "f"(lo));
    return r;
}
#define CP_COMMIT() asm volatile("cp.async.commit_group;" ::: "memory")
#define CP_WAIT1()  asm volatile("cp.async.wait_group 1;" ::: "memory")

// prefetch 3 x-rows of tile `tile` into X buffer at smem addr xbuf
__device__ __forceinline__ void prefetch_x(const float* __restrict__ x, int tile,
                                           uint32_t xbuf, int tid) {
    const int b = tile >> 7, h = tile & 127;
    for (int idx = tid; idx < 16 * 3 * 132; idx += NTHREADS) {
        int c = idx / 396;
        int rem = idx - c * 396;
        int r = rem / 132;
        int ww = rem - r * 132;
        int hh = h + r - 1, wg = ww - 1;
        bool ok = ((unsigned)hh < 128u) && ((unsigned)wg < 128u);
        int hc = ok ? hh : 0, wc = ok ? wg : 0;
        const float* g = x + ((b * 16 + c) << 14) + (hc << 7) + wc;
        int sz = ok ? 4 : 0;
        asm volatile("cp.async.ca.shared.global [%0], [%1], 4, %2;"
                     :: "r"(xbuf + (uint32_t)idx * 4), "l"(g), "r"(sz) : "memory");
    }
}

// ---------------------------------------------------------------------------
// single merged prep kernel (=> 2 launches/call => ncu -s 5 hits main kernel)
// ---------------------------------------------------------------------------
__global__ void prep_kernel(const float* __restrict__ Wx,
                            const float* __restrict__ Wy,
                            const float* __restrict__ W1,
                            const float* __restrict__ b1,
                            const float* __restrict__ bx,
                            const float* __restrict__ by,
                            const float* __restrict__ W2) {
    int idx = blockIdx.x * blockDim.x + threadIdx.x;
    if (idx < 128 * 144) {
        int m = idx / 144, k = idx - m * 144;
        int i = k / 9, kk = k - i * 9;
        const float* w1r = W1 + m * 48;
        float f = 0.f;
#pragma unroll
        for (int o = 0; o < 16; ++o) {
            f += w1r[o]      * Wx[(o * 16 + i) * 9 + kk];
            f += w1r[16 + o] * Wy[(o * 16 + i) * 9 + kk];
        }
        if (kk == 4) f += w1r[32 + i];
        __nv_bfloat16 hi = __float2bfloat16(f);
        __nv_bfloat16 lo = __float2bfloat16(f - __bfloat162float(hi));
        g_Bhi[m * 152 + k] = hi;
        g_Blo[m * 152 + k] = lo;
    }
    if (idx < 2048) {
        int o = idx >> 7, m = idx & 127;
        float f = W2[o * 128 + m];
        __nv_bfloat16 hi = __float2bfloat16(f);
        __nv_bfloat16 lo = __float2bfloat16(f - __bfloat162float(hi));
        g_W2h[o * 152 + m] = hi;
        g_W2l[o * 152 + m] = lo;
    }
    if (idx < 128) {
        float s = b1[idx];
        const float* w1r = W1 + idx * 48;
#pragma unroll
        for (int o = 0; o < 16; ++o) s += w1r[o] * bx[o] + w1r[16 + o] * by[o];
        g_B1f[idx] = s;
    }
}

// ---------------------------------------------------------------------------
__global__ __launch_bounds__(NTHREADS, 1)
void nca_mma_kernel(const float* __restrict__ x,
                    const float* __restrict__ b2g,
                    float* __restrict__ out) {
    extern __shared__ char sm[];
    float* smf = (float*)sm;
    const uint32_t smem_base = smem_u32(sm);
    const int tid = threadIdx.x;
    const int wid = tid >> 5;
    const int lane = tid & 31;
    const int q = lane & 3;
    const int mw = wid & 7;    // pixels [mw*16, +16)
    const int nw = wid >> 3;   // hidden [nw*64, +64)
    const int tile_base = blockIdx.x * TILES_PER_BLOCK;

    // ---- stage persistent weights ----
    {
        const uint4* gh = (const uint4*)g_Bhi;
        const uint4* gl = (const uint4*)g_Blo;
        uint4* shh = (uint4*)(sm + SB_BHI);
        uint4* shl = (uint4*)(sm + SB_BLO);
        for (int i = tid; i < 2432; i += NTHREADS) { shh[i] = gh[i]; shl[i] = gl[i]; }
        uint4* w2h = (uint4*)(sm + SB_W2H);
        uint4* w2l = (uint4*)(sm + SB_W2L);
        const uint4* gw2h = (const uint4*)g_W2h;
        const uint4* gw2l = (const uint4*)g_W2l;
        for (int i = tid; i < 304; i += NTHREADS) { w2h[i] = gw2h[i]; w2l[i] = gw2l[i]; }
        if (tid < 128) smf[SB_B1 / 4 + tid] = g_B1f[tid];
        if (tid < 16)  smf[SB_B2 / 4 + tid] = b2g[tid];
    }
    // prefetch tile 0's x rows while staging finishes
    prefetch_x(x, tile_base, smem_base + SB_X0, tid);
    CP_COMMIT();
    __syncthreads();

    // ---- hoist bias fragments ----
    float bini[8][2];
#pragma unroll
    for (int nt = 0; nt < 8; ++nt) {
        bini[nt][0] = smf[SB_B1 / 4 + nw * 64 + nt * 8 + q * 2];
        bini[nt][1] = smf[SB_B1 / 4 + nw * 64 + nt * 8 + q * 2 + 1];
    }
    float b2i[2][2];
#pragma unroll
    for (int jj = 0; jj < 2; ++jj) {
        b2i[jj][0] = (nw == 0) ? smf[SB_B2 / 4 + jj * 8 + q * 2] : 0.f;
        b2i[jj][1] = (nw == 0) ? smf[SB_B2 / 4 + jj * 8 + q * 2 + 1] : 0.f;
    }

    const int p_build = tid & 127;
    const int s_build = tid >> 7;          // k-slice: k in [36s, 36s+36)

    const uint32_t a_addr0 = smem_base + SB_AHI +
        (uint32_t)(mw * 16 + (lane & 7) + ((lane >> 3) & 1) * 8) * A_STRIDE_B +
        (uint32_t)((lane >> 4) * 16);
    const uint32_t b_addr0 = smem_base + SB_BHI +
        (uint32_t)(nw * 64 + (lane & 7) + (lane >> 4) * 8) * A_STRIDE_B +
        (uint32_t)(((lane >> 3) & 1) * 16);
    const uint32_t w2_addr0 = smem_base + SB_W2H +
        (uint32_t)((lane & 7) + (lane >> 4) * 8) * A_STRIDE_B +
        (uint32_t)(((lane >> 3) & 1) * 16) + (uint32_t)(nw * 128);

#pragma unroll
    for (int j = 0; j < TILES_PER_BLOCK; ++j) {
        const int tile = tile_base + j;
        const int b = tile >> 7;
        const int h = tile & 127;
        const uint32_t xcur_off = (j & 1) ? SB_X1 : SB_X0;
        const uint32_t xnext_off = (j & 1) ? SB_X0 : SB_X1;

        // prefetch next tile's x into the other buffer (clamped at the end)
        {
            int tn = tile + 1;
            if (tn > NBLOCKS * TILES_PER_BLOCK - 1) tn = NBLOCKS * TILES_PER_BLOCK - 1;
            prefetch_x(x, tn, smem_base + xnext_off, tid);
            CP_COMMIT();
        }
        CP_WAIT1();          // current tile's x resident
        __syncthreads();

        // ---- build A_hi/A_lo [p][k] bf16; thread = (pixel, 36-k slice) ----
        {
            const float* xp = smf + xcur_off / 4 + p_build;
            char* ahp = sm + SB_AHI + p_build * A_STRIDE_B + 72 * s_build;
            char* alp = sm + SB_ALO + p_build * A_STRIDE_B + 72 * s_build;
#pragma unroll
            for (int u = 0; u < 9; ++u) {
                uint32_t h2[2], l2[2];
#pragma unroll
                for (int e = 0; e < 2; ++e) {
                    int d0 = u * 4 + e * 2, d1 = d0 + 1;
                    int i0 = 4 * s_build + d0 / 9, t0 = d0 % 9;
                    int i1 = 4 * s_build + d1 / 9, t1 = d1 % 9;
                    float v0 = xp[i0 * 396 + (t0 / 3) * 132 + (t0 % 3)];
                    float v1 = xp[i1 * 396 + (t1 / 3) * 132 + (t1 % 3)];
                    uint32_t hp = cvt_bf16x2(v1, v0);
                    float f0 = __uint_as_float(hp << 16);
                    float f1 = __uint_as_float(hp & 0xFFFF0000u);
                    h2[e] = hp;
                    l2[e] = cvt_bf16x2(v1 - f1, v0 - f0);
                }
                *(uint2*)(ahp + u * 8) = make_uint2(h2[0], h2[1]);
                *(uint2*)(alp + u * 8) = make_uint2(l2[0], l2[1]);
            }
        }
        __syncthreads();

        // ---- main GEMM: M16 x N64 x K144 per warp, acc init = b1 ----
        float acc[8][4];
#pragma unroll
        for (int nt = 0; nt < 8; ++nt) {
            acc[nt][0] = bini[nt][0]; acc[nt][1] = bini[nt][1];
            acc[nt][2] = bini[nt][0]; acc[nt][3] = bini[nt][1];
        }

#pragma unroll
        for (int ks = 0; ks < 9; ++ks) {
            const uint32_t kb = (uint32_t)(ks * 32);
            uint32_t ah[4], al[4];
            ldsm_x4(ah, a_addr0 + kb);
            ldsm_x4(al, a_addr0 + kb + (SB_ALO - SB_AHI));
#pragma unroll
            for (int g = 0; g < 4; ++g) {
                uint32_t bh[4], bl[4];
                uint32_t ba = b_addr0 + (uint32_t)(g * 16) * A_STRIDE_B + kb;
                ldsm_x4(bh, ba);
                ldsm_x4(bl, ba + (SB_BLO - SB_BHI));
                mma_bf16(acc[2 * g],     ah, &bh[0]);
                mma_bf16(acc[2 * g + 1], ah, &bh[2]);
                mma_bf16(acc[2 * g],     al, &bh[0]);
                mma_bf16(acc[2 * g + 1], al, &bh[2]);
                mma_bf16(acc[2 * g],     ah, &bl[0]);
                mma_bf16(acc[2 * g + 1], ah, &bl[2]);
            }
        }

        // ---- tail GEMM over this warp's K=64 hidden half ----
        float oacc[2][4];
#pragma unroll
        for (int jj = 0; jj < 2; ++jj) {
            oacc[jj][0] = b2i[jj][0]; oacc[jj][1] = b2i[jj][1];
            oacc[jj][2] = b2i[jj][0]; oacc[jj][3] = b2i[jj][1];
        }

#pragma unroll
        for (int kt = 0; kt < 4; ++kt) {
            uint32_t wh[4], wl[4];
            uint32_t waddr = w2_addr0 + (uint32_t)(kt * 32);
            ldsm_x4(wh, waddr);
            ldsm_x4(wl, waddr + (SB_W2L - SB_W2H));
            float y0 = fmaxf(acc[2 * kt][0], 0.f),     y1 = fmaxf(acc[2 * kt][1], 0.f);
            float y2 = fmaxf(acc[2 * kt][2], 0.f),     y3 = fmaxf(acc[2 * kt][3], 0.f);
            float z0 = fmaxf(acc[2 * kt + 1][0], 0.f), z1 = fmaxf(acc[2 * kt + 1][1], 0.f);
            float z2 = fmaxf(acc[2 * kt + 1][2], 0.f), z3 = fmaxf(acc[2 * kt + 1][3], 0.f);
            uint32_t ah2[4], al2[4];
            ah2[0] = cvt_bf16x2(y1, y0);
            ah2[1] = cvt_bf16x2(y3, y2);
            ah2[2] = cvt_bf16x2(z1, z0);
            ah2[3] = cvt_bf16x2(z3, z2);
            al2[0] = cvt_bf16x2(y1 - __uint_as_float(ah2[0] & 0xFFFF0000u),
                                y0 - __uint_as_float(ah2[0] << 16));
            al2[1] = cvt_bf16x2(y3 - __uint_as_float(ah2[1] & 0xFFFF0000u),
                                y2 - __uint_as_float(ah2[1] << 16));
            al2[2] = cvt_bf16x2(z1 - __uint_as_float(ah2[2] & 0xFFFF0000u),
                                z0 - __uint_as_float(ah2[2] << 16));
            al2[3] = cvt_bf16x2(z3 - __uint_as_float(ah2[3] & 0xFFFF0000u),
                                z2 - __uint_as_float(ah2[3] << 16));
            mma_bf16(oacc[0], ah2, &wh[0]);
            mma_bf16(oacc[1], ah2, &wh[2]);
            mma_bf16(oacc[0], al2, &wh[0]);
            mma_bf16(oacc[1], al2, &wh[2]);
            mma_bf16(oacc[0], ah2, &wl[0]);
            mma_bf16(oacc[1], ah2, &wl[2]);
        }

        // ---- stage partials into the (now dead) current X buffer ----
        {
            float* obuf = smf + xcur_off / 4 + (nw ? 2560 : 0);
            int p0 = mw * 16 + (lane >> 2);
            float* s0 = obuf + p0 * 20;
            float* s1 = obuf + (p0 + 8) * 20;
            *(float2*)(s0 + 2 * q)     = make_float2(oacc[0][0], oacc[0][1]);
            *(float2*)(s0 + 8 + 2 * q) = make_float2(oacc[1][0], oacc[1][1]);
            *(float2*)(s1 + 2 * q)     = make_float2(oacc[0][2], oacc[0][3]);
            *(float2*)(s1 + 8 + 2 * q) = make_float2(oacc[1][2], oacc[1][3]);
        }
        __syncthreads();

        // ---- sum partials + coalesced store (512 thr = 512 float4: 1 pass) ----
        {
            const long obase = ((long)b << 18) + ((long)h << 4);
            const float* o0 = smf + xcur_off / 4;
            const float* o1 = o0 + 2560;
            int p = tid >> 2, c4 = (tid & 3) * 4;      // p in [0,128)
            float4 v0 = *(const float4*)(o0 + p * 20 + c4);
            float4 v1 = *(const float4*)(o1 + p * 20 + c4);
            float4 v = make_float4(v0.x + v1.x, v0.y + v1.y, v0.z + v1.z, v0.w + v1.w);
            *(float4*)(out + obase + ((long)p << 11) + c4) = v;
        }
        __syncthreads();   // staging reads done before next prefetch overwrites
    }
}

extern "C" void kernel_launch(void* const* d_in, const int* in_sizes, int n_in,
                              void* d_out, int out_size) {
    const float* x  = (const float*)d_in[0];
    const float* Wx = (const float*)d_in[1];
    const float* bx = (const float*)d_in[2];
    const float* Wy = (const float*)d_in[3];
    const float* by = (const float*)d_in[4];
    const float* W1 = (const float*)d_in[5];
    const float* b1 = (const float*)d_in[6];
    const float* W2 = (const float*)d_in[7];
    const float* b2 = (const float*)d_in[8];
    float* out = (float*)d_out;

    prep_kernel<<<72, 256>>>(Wx, Wy, W1, b1, bx, by, W2);

    cudaFuncSetAttribute(nca_mma_kernel,
                         cudaFuncAttributeMaxDynamicSharedMemorySize, SMEM_BYTES);
    nca_mma_kernel<<<NBLOCKS, NTHREADS, SMEM_BYTES>>>(x, b2, out);
}